// round 1
// baseline (speedup 1.0000x reference)
#include <cuda_runtime.h>
#include <cuda_bf16.h>

// Problem constants (fixed by the reference)
#define NN   4096   // nodes == in_channels
#define EE   65536  // edges
#define OC   200    // encoder out_channels

// Scratch (device globals: no allocation allowed)
__device__ float g_h[NN * OC];   // x @ W_rel
__device__ float g_z[NN * OC];   // x @ W_root + b_rel, then += scatter, relu'd at GEMM2 load

// ---------------------------------------------------------------------------
// GEMM1: C[4096, 400] = x[4096,4096] @ [W_rel | W_root][4096, 400]
//   cols [0,200)   -> g_h
//   cols [200,400) -> g_z (+ b_rel)
// 128x128 block tile, BK=8, 8x8 thread tile, 256 threads.
// ---------------------------------------------------------------------------
__global__ __launch_bounds__(256) void gemm1_kernel(
    const float* __restrict__ x,
    const float* __restrict__ W_rel,
    const float* __restrict__ W_root,
    const float* __restrict__ b_rel)
{
    const int bn = blockIdx.x;          // 0..3   (cols, 4*128 = 512 >= 400)
    const int bm = blockIdx.y;          // 0..31  (rows)
    const int tid = threadIdx.x;
    const int tcol = tid & 15;          // 0..15
    const int trow = tid >> 4;          // 0..15

    __shared__ float As[8][128];
    __shared__ float Bs[8][128];

    const int rowBase = bm * 128;
    const int colBase = bn * 128;

    float acc[8][8];
    #pragma unroll
    for (int i = 0; i < 8; i++)
        #pragma unroll
        for (int j = 0; j < 8; j++) acc[i][j] = 0.f;

    // A-load indexing: 128 rows x 8 cols = 1024 floats, float4 per thread
    const int ar_row = tid >> 1;
    const int ar_kk  = (tid & 1) * 4;
    // B-load indexing: 8 rows x 128 cols, 4 scalars per thread (piecewise weight)
    const int br_kk = tid >> 5;         // 0..7
    const int br_c0 = (tid & 31) * 4;   // 0..124

    for (int k0 = 0; k0 < NN; k0 += 8) {
        // A tile (transposed into As[k][r])
        {
            const float4 v = *reinterpret_cast<const float4*>(
                &x[(size_t)(rowBase + ar_row) * NN + k0 + ar_kk]);
            As[ar_kk + 0][ar_row] = v.x;
            As[ar_kk + 1][ar_row] = v.y;
            As[ar_kk + 2][ar_row] = v.z;
            As[ar_kk + 3][ar_row] = v.w;
        }
        // B tile: piecewise [W_rel | W_root], zero beyond col 400
        {
            const int k = k0 + br_kk;
            #pragma unroll
            for (int t = 0; t < 4; t++) {
                const int j = colBase + br_c0 + t;
                float v = 0.f;
                if (j < OC)            v = W_rel[k * OC + j];
                else if (j < 2 * OC)   v = W_root[k * OC + (j - OC)];
                Bs[br_kk][br_c0 + t] = v;
            }
        }
        __syncthreads();

        #pragma unroll
        for (int kk = 0; kk < 8; kk++) {
            float ar[8], br[8];
            const float4 a0 = *reinterpret_cast<const float4*>(&As[kk][trow * 8]);
            const float4 a1 = *reinterpret_cast<const float4*>(&As[kk][trow * 8 + 4]);
            const float4 b0 = *reinterpret_cast<const float4*>(&Bs[kk][tcol * 8]);
            const float4 b1 = *reinterpret_cast<const float4*>(&Bs[kk][tcol * 8 + 4]);
            ar[0]=a0.x; ar[1]=a0.y; ar[2]=a0.z; ar[3]=a0.w;
            ar[4]=a1.x; ar[5]=a1.y; ar[6]=a1.z; ar[7]=a1.w;
            br[0]=b0.x; br[1]=b0.y; br[2]=b0.z; br[3]=b0.w;
            br[4]=b1.x; br[5]=b1.y; br[6]=b1.z; br[7]=b1.w;
            #pragma unroll
            for (int i = 0; i < 8; i++)
                #pragma unroll
                for (int j = 0; j < 8; j++)
                    acc[i][j] = fmaf(ar[i], br[j], acc[i][j]);
        }
        __syncthreads();
    }

    // Epilogue: split into g_h and g_z
    #pragma unroll
    for (int i = 0; i < 8; i++) {
        const int row = rowBase + trow * 8 + i;
        #pragma unroll
        for (int j = 0; j < 8; j++) {
            const int col = colBase + tcol * 8 + j;
            if (col < OC) {
                g_h[row * OC + col] = acc[i][j];
            } else if (col < 2 * OC) {
                const int c = col - OC;
                g_z[row * OC + c] = acc[i][j] + b_rel[c];
            }
        }
    }
}

// ---------------------------------------------------------------------------
// Scatter: for each edge e: g_z[dst[e], :] += g_h[src[e], :] * w[e]
// One warp per edge; 200 cols strided over 32 lanes. g_h/g_z are L2-resident.
// ---------------------------------------------------------------------------
__global__ __launch_bounds__(256) void scatter_kernel(
    const int* __restrict__ ei,
    const float* __restrict__ ew)
{
    const int warp = (blockIdx.x * blockDim.x + threadIdx.x) >> 5;
    const int lane = threadIdx.x & 31;
    if (warp >= EE) return;
    const int src = ei[warp];
    const int dst = ei[EE + warp];
    const float w = ew[warp];
    const float* hs = &g_h[src * OC];
    float* zd = &g_z[dst * OC];
    #pragma unroll 7
    for (int c = lane; c < OC; c += 32)
        atomicAdd(&zd[c], __ldg(&hs[c]) * w);
}

// ---------------------------------------------------------------------------
// GEMM2: out[4096,4096] = relu(g_z)[4096,200] @ W_dec[200,4096] + b_dec
// Same 128x128x8 tiling; relu fused into A load; K = 200 = 25*8 exactly.
// ---------------------------------------------------------------------------
__global__ __launch_bounds__(256) void gemm2_kernel(
    const float* __restrict__ W_dec,
    const float* __restrict__ b_dec,
    float* __restrict__ out)
{
    const int bn = blockIdx.x;          // 0..31
    const int bm = blockIdx.y;          // 0..31
    const int tid = threadIdx.x;
    const int tcol = tid & 15;
    const int trow = tid >> 4;

    __shared__ float As[8][128];
    __shared__ float Bs[8][128];

    const int rowBase = bm * 128;
    const int colBase = bn * 128;

    float acc[8][8];
    #pragma unroll
    for (int i = 0; i < 8; i++)
        #pragma unroll
        for (int j = 0; j < 8; j++) acc[i][j] = 0.f;

    const int ar_row = tid >> 1;
    const int ar_kk  = (tid & 1) * 4;
    const int br_kk  = tid >> 5;
    const int br_c0  = (tid & 31) * 4;

    for (int k0 = 0; k0 < OC; k0 += 8) {
        // A tile from g_z with fused relu (row stride 200 floats = 800 B, 16B aligned)
        {
            const float4 v = *reinterpret_cast<const float4*>(
                &g_z[(size_t)(rowBase + ar_row) * OC + k0 + ar_kk]);
            As[ar_kk + 0][ar_row] = fmaxf(v.x, 0.f);
            As[ar_kk + 1][ar_row] = fmaxf(v.y, 0.f);
            As[ar_kk + 2][ar_row] = fmaxf(v.z, 0.f);
            As[ar_kk + 3][ar_row] = fmaxf(v.w, 0.f);
        }
        // B tile from W_dec (row-major [200, 4096])
        {
            const float4 v = *reinterpret_cast<const float4*>(
                &W_dec[(size_t)(k0 + br_kk) * NN + colBase + br_c0]);
            Bs[br_kk][br_c0 + 0] = v.x;
            Bs[br_kk][br_c0 + 1] = v.y;
            Bs[br_kk][br_c0 + 2] = v.z;
            Bs[br_kk][br_c0 + 3] = v.w;
        }
        __syncthreads();

        #pragma unroll
        for (int kk = 0; kk < 8; kk++) {
            float ar[8], br[8];
            const float4 a0 = *reinterpret_cast<const float4*>(&As[kk][trow * 8]);
            const float4 a1 = *reinterpret_cast<const float4*>(&As[kk][trow * 8 + 4]);
            const float4 b0 = *reinterpret_cast<const float4*>(&Bs[kk][tcol * 8]);
            const float4 b1 = *reinterpret_cast<const float4*>(&Bs[kk][tcol * 8 + 4]);
            ar[0]=a0.x; ar[1]=a0.y; ar[2]=a0.z; ar[3]=a0.w;
            ar[4]=a1.x; ar[5]=a1.y; ar[6]=a1.z; ar[7]=a1.w;
            br[0]=b0.x; br[1]=b0.y; br[2]=b0.z; br[3]=b0.w;
            br[4]=b1.x; br[5]=b1.y; br[6]=b1.z; br[7]=b1.w;
            #pragma unroll
            for (int i = 0; i < 8; i++)
                #pragma unroll
                for (int j = 0; j < 8; j++)
                    acc[i][j] = fmaf(ar[i], br[j], acc[i][j]);
        }
        __syncthreads();
    }

    // Epilogue: + b_dec, vectorized stores
    #pragma unroll
    for (int i = 0; i < 8; i++) {
        const int row = rowBase + trow * 8 + i;
        const int col = colBase + tcol * 8;
        float4 o0, o1;
        o0.x = acc[i][0] + b_dec[col + 0];
        o0.y = acc[i][1] + b_dec[col + 1];
        o0.z = acc[i][2] + b_dec[col + 2];
        o0.w = acc[i][3] + b_dec[col + 3];
        o1.x = acc[i][4] + b_dec[col + 4];
        o1.y = acc[i][5] + b_dec[col + 5];
        o1.z = acc[i][6] + b_dec[col + 6];
        o1.w = acc[i][7] + b_dec[col + 7];
        *reinterpret_cast<float4*>(&out[(size_t)row * NN + col]) = o0;
        *reinterpret_cast<float4*>(&out[(size_t)row * NN + col + 4]) = o1;
    }
}

// ---------------------------------------------------------------------------
// Launch
// Inputs (metadata order): x, edge_index, edge_weight, W_rel, b_rel, W_root,
//                          W_dec, b_dec
// ---------------------------------------------------------------------------
extern "C" void kernel_launch(void* const* d_in, const int* in_sizes, int n_in,
                              void* d_out, int out_size)
{
    const float* x      = (const float*)d_in[0];
    const int*   ei     = (const int*)  d_in[1];
    const float* ew     = (const float*)d_in[2];
    const float* W_rel  = (const float*)d_in[3];
    const float* b_rel  = (const float*)d_in[4];
    const float* W_root = (const float*)d_in[5];
    const float* W_dec  = (const float*)d_in[6];
    const float* b_dec  = (const float*)d_in[7];
    float* out = (float*)d_out;

    dim3 g1(4, 32);    // cols: 4 tiles of 128 covering 400; rows: 32
    gemm1_kernel<<<g1, 256>>>(x, W_rel, W_root, b_rel);

    // 65536 edges, 1 warp each -> 65536 warps -> 8192 blocks of 256 threads
    scatter_kernel<<<8192, 256>>>(ei, ew);

    dim3 g2(32, 32);
    gemm2_kernel<<<g2, 256>>>(W_dec, b_dec, out);
}

// round 3
// speedup vs baseline: 4.6243x; 4.6243x over previous
#include <cuda_runtime.h>
#include <cuda_bf16.h>
#include <stdint.h>

#define NN   4096
#define EE   65536
#define OC   200
#define KPAD 256    // padded K for GEMM2
#define NCAT 512    // padded N for GEMM1 weight concat

// ---------------------------------------------------------------------------
// Scratch (device globals; no runtime allocation allowed)
// ---------------------------------------------------------------------------
__device__ __align__(16) __nv_bfloat16 g_xhi[(size_t)NN * NN];   // 32 MB
__device__ __align__(16) __nv_bfloat16 g_xlo[(size_t)NN * NN];   // 32 MB
__device__ __align__(16) __nv_bfloat16 g_w1hi[NCAT * NN];        // [n,k] = Wcat[k,n]
__device__ __align__(16) __nv_bfloat16 g_w1lo[NCAT * NN];
__device__ __align__(16) float g_h[NN * OC];
__device__ __align__(16) float g_z[NN * OC];
__device__ __align__(16) __nv_bfloat16 g_zhi[NN * KPAD];         // relu(z) split, K-padded
__device__ __align__(16) __nv_bfloat16 g_zlo[NN * KPAD];
__device__ __align__(16) __nv_bfloat16 g_wdhi[NN * KPAD];        // [n,k] = W_dec[k,n], padded
__device__ __align__(16) __nv_bfloat16 g_wdlo[NN * KPAD];

// ---------------------------------------------------------------------------
// PTX helpers (sm_100 baseline target: NO tcgen05; use ldmatrix + mma.sync)
// ---------------------------------------------------------------------------
__device__ __forceinline__ uint32_t smem_u32(const void* p) {
    uint32_t a;
    asm("{ .reg .u64 t; cvta.to.shared.u64 t, %1; cvt.u32.u64 %0, t; }" : "=r"(a) : "l"(p));
    return a;
}
#define CP16(sa, gp)  asm volatile("cp.async.cg.shared.global [%0], [%1], 16;" :: "r"(sa), "l"(gp))
#define CP_COMMIT()   asm volatile("cp.async.commit_group;" ::: "memory")
#define CP_WAIT(n)    asm volatile("cp.async.wait_group %0;" :: "n"(n) : "memory")

__device__ __forceinline__ void ldsm_x4(uint32_t* r, uint32_t addr) {
    asm volatile("ldmatrix.sync.aligned.m8n8.x4.shared.b16 {%0,%1,%2,%3}, [%4];"
                 : "=r"(r[0]), "=r"(r[1]), "=r"(r[2]), "=r"(r[3]) : "r"(addr));
}
__device__ __forceinline__ void ldsm_x2(uint32_t* r, uint32_t addr) {
    asm volatile("ldmatrix.sync.aligned.m8n8.x2.shared.b16 {%0,%1}, [%2];"
                 : "=r"(r[0]), "=r"(r[1]) : "r"(addr));
}
__device__ __forceinline__ void mma16816(float* d, const uint32_t* a, const uint32_t* b) {
    asm volatile("mma.sync.aligned.m16n8k16.row.col.f32.bf16.bf16.f32 "
                 "{%0,%1,%2,%3}, {%4,%5,%6,%7}, {%8,%9}, {%0,%1,%2,%3};"
                 : "+f"(d[0]), "+f"(d[1]), "+f"(d[2]), "+f"(d[3])
                 : "r"(a[0]), "r"(a[1]), "r"(a[2]), "r"(a[3]), "r"(b[0]), "r"(b[1]));
}

// SW128-style swizzle for 128-byte rows: off ^ ((off>>3)&0x70)
__device__ __forceinline__ uint32_t tile_addr(uint32_t base, int row, int kbyte) {
    uint32_t off = row * 128 + kbyte;
    return base + (off ^ ((off >> 3) & 0x70));
}

// SMEM: 2 buffers x 4 tiles (Ahi, Alo, Bhi, Blo) x 16KB (128 rows x 128B)
#define TILE_B     16384
#define BUF_B      (4 * TILE_B)
#define SMEM_TOTAL (2 * BUF_B)   // 131072

// Fill one 128-row x 64-col bf16 tile (swizzled), 256 threads, 4x16B each.
__device__ __forceinline__ void fill_tile(uint32_t sbase, const __nv_bfloat16* __restrict__ gsrc,
                                          int row0, int stride, int k0) {
    const int tid = threadIdx.x;
    #pragma unroll
    for (int t = 0; t < 4; t++) {
        const int q = tid + t * 256;              // 0..1023 16B chunks
        const int r = q >> 3;
        const int c16 = q & 7;
        uint32_t off = r * 128 + c16 * 16;
        uint32_t sw = off ^ ((off >> 3) & 0x70);
        const void* gp = gsrc + (size_t)(row0 + r) * stride + k0 + c16 * 8;
        CP16(sbase + sw, gp);
    }
}

// ---------------------------------------------------------------------------
// Conversion kernels (fp32 -> bf16 hi/lo split)
// ---------------------------------------------------------------------------
__device__ __forceinline__ void split2(float v, __nv_bfloat16& h, __nv_bfloat16& l) {
    h = __float2bfloat16(v);
    l = __float2bfloat16(v - __bfloat162float(h));
}

__global__ __launch_bounds__(256) void conv_x_kernel(const float* __restrict__ x) {
    const size_t i = ((size_t)blockIdx.x * 256 + threadIdx.x) * 4;
    float4 v = *reinterpret_cast<const float4*>(x + i);
    __nv_bfloat16 h0, h1, h2, h3, l0, l1, l2, l3;
    split2(v.x, h0, l0); split2(v.y, h1, l1); split2(v.z, h2, l2); split2(v.w, h3, l3);
    *reinterpret_cast<__nv_bfloat162*>(g_xhi + i)     = __nv_bfloat162(h0, h1);
    *reinterpret_cast<__nv_bfloat162*>(g_xhi + i + 2) = __nv_bfloat162(h2, h3);
    *reinterpret_cast<__nv_bfloat162*>(g_xlo + i)     = __nv_bfloat162(l0, l1);
    *reinterpret_cast<__nv_bfloat162*>(g_xlo + i + 2) = __nv_bfloat162(l2, l3);
}

__global__ __launch_bounds__(256) void conv_w1_kernel(const float* __restrict__ W_rel,
                                                      const float* __restrict__ W_root) {
    const int idx = blockIdx.x * 256 + threadIdx.x;   // n*4096 + k, n<512
    const int n = idx >> 12, k = idx & 4095;
    float v = 0.f;
    if (n < OC)          v = W_rel[k * OC + n];
    else if (n < 2 * OC) v = W_root[k * OC + (n - OC)];
    __nv_bfloat16 h, l; split2(v, h, l);
    g_w1hi[idx] = h; g_w1lo[idx] = l;
}

__global__ __launch_bounds__(256) void conv_wdec_kernel(const float* __restrict__ W_dec) {
    const int idx = blockIdx.x * 256 + threadIdx.x;   // n*256 + k
    const int n = idx >> 8, k = idx & 255;
    float v = (k < OC) ? W_dec[(size_t)k * NN + n] : 0.f;
    __nv_bfloat16 h, l; split2(v, h, l);
    g_wdhi[idx] = h; g_wdlo[idx] = l;
}

__global__ __launch_bounds__(256) void conv_z_kernel() {
    const int idx = blockIdx.x * 256 + threadIdx.x;   // m*256 + k
    const int m = idx >> 8, k = idx & 255;
    float v = (k < OC) ? fmaxf(g_z[m * OC + k], 0.f) : 0.f;
    __nv_bfloat16 h, l; split2(v, h, l);
    g_zhi[idx] = h; g_zlo[idx] = l;
}

// ---------------------------------------------------------------------------
// Edge scatter: g_z[dst] += g_h[src] * w   (vectorized f32 reductions)
// ---------------------------------------------------------------------------
__global__ __launch_bounds__(256) void scatter_kernel(const int* __restrict__ ei,
                                                      const float* __restrict__ ew) {
    const int warp = (blockIdx.x * 256 + threadIdx.x) >> 5;
    const int lane = threadIdx.x & 31;
    if (warp >= EE) return;
    const int src = ei[warp];
    const int dst = ei[EE + warp];
    const float w = ew[warp];
    const float4* hs = reinterpret_cast<const float4*>(&g_h[src * OC]);
    float4* zd = reinterpret_cast<float4*>(&g_z[dst * OC]);
    #pragma unroll 2
    for (int c = lane; c < OC / 4; c += 32) {
        const float4 v = __ldg(hs + c);
        asm volatile("red.global.add.v4.f32 [%0], {%1, %2, %3, %4};"
                     :: "l"(zd + c), "f"(v.x * w), "f"(v.y * w), "f"(v.z * w), "f"(v.w * w)
                     : "memory");
    }
}

// ---------------------------------------------------------------------------
// mma.sync mainloop: 128x128 CTA tile, BK=64, 8 warps (2 row x 4 col),
// warp tile 64x32; split-bf16 3-MMA compensation; double-buffered cp.async.
// acc[mi][ni][4]: mi 0..3 (m16 frags), ni 0..3 (n8 frags).
// ---------------------------------------------------------------------------
__device__ __forceinline__ void mma_mainloop(float acc[4][4][4], uint32_t sb, int niter,
    const __nv_bfloat16* Ahi, const __nv_bfloat16* Alo, int arow0, int astride,
    const __nv_bfloat16* Bhi, const __nv_bfloat16* Blo, int brow0, int bstride)
{
    const int wid = threadIdx.x >> 5;
    const int lane = threadIdx.x & 31;
    const int wrbase = (wid >> 2) * 64;   // warp row base (0 or 64)
    const int wcbase = (wid & 3) * 32;    // warp col base (0,32,64,96)

    // ldmatrix lane addressing (within-tile row / k-byte)
    const int a_row = wrbase + (lane & 15);
    const int a_kb  = (lane >> 4) * 16;
    const int b_row = wcbase + (lane & 7);
    const int b_kb  = ((lane >> 3) & 1) * 16;

    // prologue fill of buffer 0
    fill_tile(sb + 0 * TILE_B, Ahi, arow0, astride, 0);
    fill_tile(sb + 1 * TILE_B, Alo, arow0, astride, 0);
    fill_tile(sb + 2 * TILE_B, Bhi, brow0, bstride, 0);
    fill_tile(sb + 3 * TILE_B, Blo, brow0, bstride, 0);
    CP_COMMIT();

    for (int iter = 0; iter < niter; ++iter) {
        const int b = iter & 1;
        if (iter + 1 < niter) {
            const uint32_t bn = sb + (1 - b) * BUF_B;
            const int k0 = (iter + 1) * 64;
            fill_tile(bn + 0 * TILE_B, Ahi, arow0, astride, k0);
            fill_tile(bn + 1 * TILE_B, Alo, arow0, astride, k0);
            fill_tile(bn + 2 * TILE_B, Bhi, brow0, bstride, k0);
            fill_tile(bn + 3 * TILE_B, Blo, brow0, bstride, k0);
            CP_COMMIT();
            CP_WAIT(1);
        } else {
            CP_WAIT(0);
        }
        __syncthreads();

        const uint32_t tAh = sb + b * BUF_B + 0 * TILE_B;
        const uint32_t tAl = sb + b * BUF_B + 1 * TILE_B;
        const uint32_t tBh = sb + b * BUF_B + 2 * TILE_B;
        const uint32_t tBl = sb + b * BUF_B + 3 * TILE_B;

        #pragma unroll
        for (int ks = 0; ks < 4; ks++) {
            uint32_t ah[4][4], al[4][4], bh[4][2], bl[4][2];
            #pragma unroll
            for (int mi = 0; mi < 4; mi++) {
                ldsm_x4(ah[mi], tile_addr(tAh, a_row + mi * 16, ks * 32 + a_kb));
                ldsm_x4(al[mi], tile_addr(tAl, a_row + mi * 16, ks * 32 + a_kb));
            }
            #pragma unroll
            for (int ni = 0; ni < 4; ni++) {
                ldsm_x2(bh[ni], tile_addr(tBh, b_row + ni * 8, ks * 32 + b_kb));
                ldsm_x2(bl[ni], tile_addr(tBl, b_row + ni * 8, ks * 32 + b_kb));
            }
            #pragma unroll
            for (int mi = 0; mi < 4; mi++)
                #pragma unroll
                for (int ni = 0; ni < 4; ni++) {
                    mma16816(acc[mi][ni], ah[mi], bh[ni]);
                    mma16816(acc[mi][ni], ah[mi], bl[ni]);
                    mma16816(acc[mi][ni], al[mi], bh[ni]);
                }
        }
        __syncthreads();
    }
}

// ---------------------------------------------------------------------------
// GEMM1: [g_h | g_z] (4096 x 400) = x @ [W_rel | W_root]    grid (4, 32)
// ---------------------------------------------------------------------------
__global__ __launch_bounds__(256) void gemm1_mma(const float* __restrict__ b_rel) {
    extern __shared__ __align__(1024) char smem[];
    const uint32_t sb = smem_u32(smem);
    const int rowBase = blockIdx.y * 128;
    const int colBase = blockIdx.x * 128;

    float acc[4][4][4];
    #pragma unroll
    for (int i = 0; i < 4; i++)
        #pragma unroll
        for (int j = 0; j < 4; j++)
            #pragma unroll
            for (int t = 0; t < 4; t++) acc[i][j][t] = 0.f;

    mma_mainloop(acc, sb, NN / 64, g_xhi, g_xlo, rowBase, NN, g_w1hi, g_w1lo, colBase, NN);

    const int wid = threadIdx.x >> 5, lane = threadIdx.x & 31;
    const int wrbase = (wid >> 2) * 64, wcbase = (wid & 3) * 32;
    #pragma unroll
    for (int mi = 0; mi < 4; mi++) {
        #pragma unroll
        for (int ni = 0; ni < 4; ni++) {
            const int r0 = rowBase + wrbase + mi * 16 + (lane >> 2);
            const int gc = colBase + wcbase + ni * 8 + (lane & 3) * 2;
            #pragma unroll
            for (int h = 0; h < 2; h++) {        // row, row+8
                const int r = r0 + h * 8;
                const float v0 = acc[mi][ni][h * 2 + 0];
                const float v1 = acc[mi][ni][h * 2 + 1];
                if (gc < OC) {
                    g_h[r * OC + gc] = v0;
                    g_h[r * OC + gc + 1] = v1;
                } else if (gc < 2 * OC) {
                    const int c = gc - OC;
                    g_z[r * OC + c] = v0 + __ldg(&b_rel[c]);
                    if (c + 1 < OC) g_z[r * OC + c + 1] = v1 + __ldg(&b_rel[c + 1]);
                }
            }
        }
    }
}

// ---------------------------------------------------------------------------
// GEMM2: out (4096 x 4096) = relu(z) @ W_dec + b_dec    grid (32, 32)
// ---------------------------------------------------------------------------
__global__ __launch_bounds__(256) void gemm2_mma(const float* __restrict__ b_dec,
                                                 float* __restrict__ out) {
    extern __shared__ __align__(1024) char smem[];
    const uint32_t sb = smem_u32(smem);
    const int rowBase = blockIdx.y * 128;
    const int colBase = blockIdx.x * 128;

    float acc[4][4][4];
    #pragma unroll
    for (int i = 0; i < 4; i++)
        #pragma unroll
        for (int j = 0; j < 4; j++)
            #pragma unroll
            for (int t = 0; t < 4; t++) acc[i][j][t] = 0.f;

    mma_mainloop(acc, sb, KPAD / 64, g_zhi, g_zlo, rowBase, KPAD, g_wdhi, g_wdlo, colBase, KPAD);

    const int wid = threadIdx.x >> 5, lane = threadIdx.x & 31;
    const int wrbase = (wid >> 2) * 64, wcbase = (wid & 3) * 32;
    #pragma unroll
    for (int mi = 0; mi < 4; mi++) {
        #pragma unroll
        for (int ni = 0; ni < 4; ni++) {
            const int r0 = rowBase + wrbase + mi * 16 + (lane >> 2);
            const int gc = colBase + wcbase + ni * 8 + (lane & 3) * 2;
            const float b0 = __ldg(&b_dec[gc]);
            const float b1 = __ldg(&b_dec[gc + 1]);
            #pragma unroll
            for (int h = 0; h < 2; h++) {
                const int r = r0 + h * 8;
                float2 o;
                o.x = acc[mi][ni][h * 2 + 0] + b0;
                o.y = acc[mi][ni][h * 2 + 1] + b1;
                *reinterpret_cast<float2*>(&out[(size_t)r * NN + gc]) = o;
            }
        }
    }
}

// ---------------------------------------------------------------------------
// Launch.  Inputs: x, edge_index, edge_weight, W_rel, b_rel, W_root, W_dec, b_dec
// ---------------------------------------------------------------------------
extern "C" void kernel_launch(void* const* d_in, const int* in_sizes, int n_in,
                              void* d_out, int out_size) {
    const float* x      = (const float*)d_in[0];
    const int*   ei     = (const int*)  d_in[1];
    const float* ew     = (const float*)d_in[2];
    const float* W_rel  = (const float*)d_in[3];
    const float* b_rel  = (const float*)d_in[4];
    const float* W_root = (const float*)d_in[5];
    const float* W_dec  = (const float*)d_in[6];
    const float* b_dec  = (const float*)d_in[7];
    float* out = (float*)d_out;

    cudaFuncSetAttribute(gemm1_mma, cudaFuncAttributeMaxDynamicSharedMemorySize, SMEM_TOTAL);
    cudaFuncSetAttribute(gemm2_mma, cudaFuncAttributeMaxDynamicSharedMemorySize, SMEM_TOTAL);

    conv_x_kernel<<<16384, 256>>>(x);
    conv_w1_kernel<<<8192, 256>>>(W_rel, W_root);
    conv_wdec_kernel<<<4096, 256>>>(W_dec);

    gemm1_mma<<<dim3(4, 32), 256, SMEM_TOTAL>>>(b_rel);
    scatter_kernel<<<8192, 256>>>(ei, ew);
    conv_z_kernel<<<4096, 256>>>();
    gemm2_mma<<<dim3(32, 32), 256, SMEM_TOTAL>>>(b_dec, out);
}

// round 4
// speedup vs baseline: 4.9495x; 1.0703x over previous
#include <cuda_runtime.h>
#include <cuda_bf16.h>
#include <stdint.h>

#define NN   4096
#define EE   65536
#define OC   200
#define KPAD 256    // padded K for GEMM2
#define NCAT 512    // padded N for GEMM1 weight concat

// ---------------------------------------------------------------------------
// Scratch (device globals; no runtime allocation allowed)
// ---------------------------------------------------------------------------
__device__ __align__(16) __nv_bfloat16 g_xhi[(size_t)NN * NN];   // 32 MB
__device__ __align__(16) __nv_bfloat16 g_xlo[(size_t)NN * NN];   // 32 MB
__device__ __align__(16) __nv_bfloat16 g_w1hi[NCAT * NN];        // [n,k] = Wcat[k,n]
__device__ __align__(16) __nv_bfloat16 g_w1lo[NCAT * NN];
__device__ __align__(16) float g_h[NN * OC];
__device__ __align__(16) float g_z[NN * OC];
__device__ __align__(16) __nv_bfloat16 g_zhi[NN * KPAD];         // relu(z) split, K-padded
__device__ __align__(16) __nv_bfloat16 g_zlo[NN * KPAD];
__device__ __align__(16) __nv_bfloat16 g_wdhi[NN * KPAD];        // [n,k] = W_dec[k,n], padded
__device__ __align__(16) __nv_bfloat16 g_wdlo[NN * KPAD];

// ---------------------------------------------------------------------------
// PTX helpers (sm_100 baseline target: ldmatrix + mma.sync)
// ---------------------------------------------------------------------------
__device__ __forceinline__ uint32_t smem_u32(const void* p) {
    uint32_t a;
    asm("{ .reg .u64 t; cvta.to.shared.u64 t, %1; cvt.u32.u64 %0, t; }" : "=r"(a) : "l"(p));
    return a;
}
#define CP16(sa, gp)  asm volatile("cp.async.cg.shared.global [%0], [%1], 16;" :: "r"(sa), "l"(gp))
#define CP_COMMIT()   asm volatile("cp.async.commit_group;" ::: "memory")
#define CP_WAIT(n)    asm volatile("cp.async.wait_group %0;" :: "n"(n) : "memory")

__device__ __forceinline__ void ldsm_x4(uint32_t* r, uint32_t addr) {
    asm volatile("ldmatrix.sync.aligned.m8n8.x4.shared.b16 {%0,%1,%2,%3}, [%4];"
                 : "=r"(r[0]), "=r"(r[1]), "=r"(r[2]), "=r"(r[3]) : "r"(addr));
}
__device__ __forceinline__ void ldsm_x2(uint32_t* r, uint32_t addr) {
    asm volatile("ldmatrix.sync.aligned.m8n8.x2.shared.b16 {%0,%1}, [%2];"
                 : "=r"(r[0]), "=r"(r[1]) : "r"(addr));
}
__device__ __forceinline__ void mma16816(float* d, const uint32_t* a, const uint32_t* b) {
    asm volatile("mma.sync.aligned.m16n8k16.row.col.f32.bf16.bf16.f32 "
                 "{%0,%1,%2,%3}, {%4,%5,%6,%7}, {%8,%9}, {%0,%1,%2,%3};"
                 : "+f"(d[0]), "+f"(d[1]), "+f"(d[2]), "+f"(d[3])
                 : "r"(a[0]), "r"(a[1]), "r"(a[2]), "r"(a[3]), "r"(b[0]), "r"(b[1]));
}

// SW128-style swizzle for 128-byte rows
__device__ __forceinline__ uint32_t tile_addr(uint32_t base, int row, int kbyte) {
    uint32_t off = row * 128 + kbyte;
    return base + (off ^ ((off >> 3) & 0x70));
}

// SMEM: 3 stages x 4 tiles (Ahi, Alo, Bhi, Blo) x 16KB (128 rows x 128B)
#define TILE_B     16384
#define BUF_B      (4 * TILE_B)          // 64 KB per stage
#define NSTAGE     3
#define SMEM_TOTAL (NSTAGE * BUF_B)      // 196608

// Fill one 128-row x 64-col bf16 tile (swizzled), 256 threads, 4x16B each.
__device__ __forceinline__ void fill_tile(uint32_t sbase, const __nv_bfloat16* __restrict__ gsrc,
                                          int row0, int stride, int k0) {
    const int tid = threadIdx.x;
    #pragma unroll
    for (int t = 0; t < 4; t++) {
        const int q = tid + t * 256;              // 0..1023 16B chunks
        const int r = q >> 3;
        const int c16 = q & 7;
        uint32_t off = r * 128 + c16 * 16;
        uint32_t sw = off ^ ((off >> 3) & 0x70);
        const void* gp = gsrc + (size_t)(row0 + r) * stride + k0 + c16 * 8;
        CP16(sbase + sw, gp);
    }
}

__device__ __forceinline__ void fill_stage(uint32_t sbase, int k0,
    const __nv_bfloat16* Ahi, const __nv_bfloat16* Alo, int arow0, int astride,
    const __nv_bfloat16* Bhi, const __nv_bfloat16* Blo, int brow0, int bstride)
{
    fill_tile(sbase + 0 * TILE_B, Ahi, arow0, astride, k0);
    fill_tile(sbase + 1 * TILE_B, Alo, arow0, astride, k0);
    fill_tile(sbase + 2 * TILE_B, Bhi, brow0, bstride, k0);
    fill_tile(sbase + 3 * TILE_B, Blo, brow0, bstride, k0);
}

// ---------------------------------------------------------------------------
// Merged preprocessing kernel: x split + both weight transposes/splits
//   blocks [0, 16384)           : x -> g_xhi/g_xlo        (4 floats/thread)
//   blocks [16384, 24576)       : W_rel|W_root -> g_w1*   (1 elem/thread)
//   blocks [24576, 28672)       : W_dec -> g_wd*          (1 elem/thread)
// ---------------------------------------------------------------------------
__device__ __forceinline__ void split2(float v, __nv_bfloat16& h, __nv_bfloat16& l) {
    h = __float2bfloat16(v);
    l = __float2bfloat16(v - __bfloat162float(h));
}

__global__ __launch_bounds__(256) void conv_pre_kernel(
    const float* __restrict__ x,
    const float* __restrict__ W_rel, const float* __restrict__ W_root,
    const float* __restrict__ W_dec)
{
    const int bid = blockIdx.x;
    if (bid < 16384) {
        const size_t i = ((size_t)bid * 256 + threadIdx.x) * 4;
        float4 v = *reinterpret_cast<const float4*>(x + i);
        __nv_bfloat16 h0, h1, h2, h3, l0, l1, l2, l3;
        split2(v.x, h0, l0); split2(v.y, h1, l1); split2(v.z, h2, l2); split2(v.w, h3, l3);
        *reinterpret_cast<__nv_bfloat162*>(g_xhi + i)     = __nv_bfloat162(h0, h1);
        *reinterpret_cast<__nv_bfloat162*>(g_xhi + i + 2) = __nv_bfloat162(h2, h3);
        *reinterpret_cast<__nv_bfloat162*>(g_xlo + i)     = __nv_bfloat162(l0, l1);
        *reinterpret_cast<__nv_bfloat162*>(g_xlo + i + 2) = __nv_bfloat162(l2, l3);
    } else if (bid < 24576) {
        const int idx = (bid - 16384) * 256 + threadIdx.x;   // n*4096 + k, n<512
        const int n = idx >> 12, k = idx & 4095;
        float v = 0.f;
        if (n < OC)          v = W_rel[k * OC + n];
        else if (n < 2 * OC) v = W_root[k * OC + (n - OC)];
        __nv_bfloat16 h, l; split2(v, h, l);
        g_w1hi[idx] = h; g_w1lo[idx] = l;
    } else {
        const int idx = (bid - 24576) * 256 + threadIdx.x;   // n*256 + k
        const int n = idx >> 8, k = idx & 255;
        float v = (k < OC) ? W_dec[(size_t)k * NN + n] : 0.f;
        __nv_bfloat16 h, l; split2(v, h, l);
        g_wdhi[idx] = h; g_wdlo[idx] = l;
    }
}

// relu(z) split, vectorized 8 elems/thread.  grid 512 x 256.
__global__ __launch_bounds__(256) void conv_z_kernel() {
    const int idx = blockIdx.x * 256 + threadIdx.x;   // each: row m, cols kk..kk+7
    const int m = idx >> 5;
    const int kk = (idx & 31) * 8;
    __nv_bfloat162 h[4], l[4];
    if (kk < OC) {
        const float4 v0 = *reinterpret_cast<const float4*>(&g_z[m * OC + kk]);
        const float4 v1 = *reinterpret_cast<const float4*>(&g_z[m * OC + kk + 4]);
        float f[8] = {v0.x, v0.y, v0.z, v0.w, v1.x, v1.y, v1.z, v1.w};
        #pragma unroll
        for (int t = 0; t < 4; t++) {
            __nv_bfloat16 h0, h1, l0, l1;
            split2(fmaxf(f[2 * t], 0.f), h0, l0);
            split2(fmaxf(f[2 * t + 1], 0.f), h1, l1);
            h[t] = __nv_bfloat162(h0, h1);
            l[t] = __nv_bfloat162(l0, l1);
        }
    } else {
        #pragma unroll
        for (int t = 0; t < 4; t++) {
            h[t] = __nv_bfloat162(__float2bfloat16(0.f), __float2bfloat16(0.f));
            l[t] = h[t];
        }
    }
    #pragma unroll
    for (int t = 0; t < 4; t++) {
        *reinterpret_cast<__nv_bfloat162*>(g_zhi + m * KPAD + kk + 2 * t) = h[t];
        *reinterpret_cast<__nv_bfloat162*>(g_zlo + m * KPAD + kk + 2 * t) = l[t];
    }
}

// ---------------------------------------------------------------------------
// Edge scatter: g_z[dst] += g_h[src] * w
// ---------------------------------------------------------------------------
__global__ __launch_bounds__(256) void scatter_kernel(const int* __restrict__ ei,
                                                      const float* __restrict__ ew) {
    const int warp = (blockIdx.x * 256 + threadIdx.x) >> 5;
    const int lane = threadIdx.x & 31;
    if (warp >= EE) return;
    const int src = ei[warp];
    const int dst = ei[EE + warp];
    const float w = ew[warp];
    const float4* hs = reinterpret_cast<const float4*>(&g_h[src * OC]);
    float4* zd = reinterpret_cast<float4*>(&g_z[dst * OC]);
    #pragma unroll 2
    for (int c = lane; c < OC / 4; c += 32) {
        const float4 v = __ldg(hs + c);
        asm volatile("red.global.add.v4.f32 [%0], {%1, %2, %3, %4};"
                     :: "l"(zd + c), "f"(v.x * w), "f"(v.y * w), "f"(v.z * w), "f"(v.w * w)
                     : "memory");
    }
}

// ---------------------------------------------------------------------------
// mma.sync mainloop: 128x128 CTA tile, BK=64, 8 warps (2 row x 4 col),
// warp tile 64x32; split-bf16 3-MMA; 3-stage cp.async pipeline, 1 sync/iter.
// last_ks: number of k16-steps (of 4) active in the final iteration.
// ---------------------------------------------------------------------------
__device__ __forceinline__ void mma_mainloop(float acc[4][4][4], uint32_t sb,
    int niter, int last_ks,
    const __nv_bfloat16* Ahi, const __nv_bfloat16* Alo, int arow0, int astride,
    const __nv_bfloat16* Bhi, const __nv_bfloat16* Blo, int brow0, int bstride)
{
    const int wid = threadIdx.x >> 5;
    const int lane = threadIdx.x & 31;
    const int wrbase = (wid >> 2) * 64;   // warp row base (0 or 64)
    const int wcbase = (wid & 3) * 32;    // warp col base (0,32,64,96)

    const int a_row = wrbase + (lane & 15);
    const int a_kb  = (lane >> 4) * 16;
    const int b_row = wcbase + (lane & 7);
    const int b_kb  = ((lane >> 3) & 1) * 16;

    // prologue: fill stages 0 and 1
    fill_stage(sb + 0 * BUF_B, 0, Ahi, Alo, arow0, astride, Bhi, Blo, brow0, bstride);
    CP_COMMIT();
    fill_stage(sb + 1 * BUF_B, 64, Ahi, Alo, arow0, astride, Bhi, Blo, brow0, bstride);
    CP_COMMIT();

    int st = 0;                // stage being consumed
    int fill_st = 2;           // stage to fill this iteration
    for (int iter = 0; iter < niter; ++iter) {
        CP_WAIT(1);            // stage `st` complete (exactly 2 groups pending at entry)
        __syncthreads();       // also: all warps done reading the stage `fill_st` overwrites

        if (iter + 2 < niter)
            fill_stage(sb + fill_st * BUF_B, (iter + 2) * 64,
                       Ahi, Alo, arow0, astride, Bhi, Blo, brow0, bstride);
        CP_COMMIT();           // always commit (possibly empty) to keep the count exact

        const uint32_t tAh = sb + st * BUF_B + 0 * TILE_B;
        const uint32_t tAl = sb + st * BUF_B + 1 * TILE_B;
        const uint32_t tBh = sb + st * BUF_B + 2 * TILE_B;
        const uint32_t tBl = sb + st * BUF_B + 3 * TILE_B;
        const int nks = (iter == niter - 1) ? last_ks : 4;

        #pragma unroll
        for (int ks = 0; ks < 4; ks++) {
            if (ks >= nks) break;
            uint32_t ah[4][4], al[4][4], bh[4][2], bl[4][2];
            #pragma unroll
            for (int mi = 0; mi < 4; mi++) {
                ldsm_x4(ah[mi], tile_addr(tAh, a_row + mi * 16, ks * 32 + a_kb));
                ldsm_x4(al[mi], tile_addr(tAl, a_row + mi * 16, ks * 32 + a_kb));
            }
            #pragma unroll
            for (int ni = 0; ni < 4; ni++) {
                ldsm_x2(bh[ni], tile_addr(tBh, b_row + ni * 8, ks * 32 + b_kb));
                ldsm_x2(bl[ni], tile_addr(tBl, b_row + ni * 8, ks * 32 + b_kb));
            }
            #pragma unroll
            for (int mi = 0; mi < 4; mi++)
                #pragma unroll
                for (int ni = 0; ni < 4; ni++) {
                    mma16816(acc[mi][ni], ah[mi], bh[ni]);
                    mma16816(acc[mi][ni], ah[mi], bl[ni]);
                    mma16816(acc[mi][ni], al[mi], bh[ni]);
                }
        }
        st = (st == NSTAGE - 1) ? 0 : st + 1;
        fill_st = (fill_st == NSTAGE - 1) ? 0 : fill_st + 1;
    }
}

// ---------------------------------------------------------------------------
// GEMM1: [g_h | g_z] (4096 x 400) = x @ [W_rel | W_root]    grid (4, 32)
// ---------------------------------------------------------------------------
__global__ __launch_bounds__(256) void gemm1_mma(const float* __restrict__ b_rel) {
    extern __shared__ __align__(1024) char smem[];
    const uint32_t sb = smem_u32(smem);
    const int rowBase = blockIdx.y * 128;
    const int colBase = blockIdx.x * 128;

    float acc[4][4][4];
    #pragma unroll
    for (int i = 0; i < 4; i++)
        #pragma unroll
        for (int j = 0; j < 4; j++)
            #pragma unroll
            for (int t = 0; t < 4; t++) acc[i][j][t] = 0.f;

    mma_mainloop(acc, sb, NN / 64, 4, g_xhi, g_xlo, rowBase, NN, g_w1hi, g_w1lo, colBase, NN);

    const int wid = threadIdx.x >> 5, lane = threadIdx.x & 31;
    const int wrbase = (wid >> 2) * 64, wcbase = (wid & 3) * 32;
    #pragma unroll
    for (int mi = 0; mi < 4; mi++) {
        #pragma unroll
        for (int ni = 0; ni < 4; ni++) {
            const int r0 = rowBase + wrbase + mi * 16 + (lane >> 2);
            const int gc = colBase + wcbase + ni * 8 + (lane & 3) * 2;
            #pragma unroll
            for (int h = 0; h < 2; h++) {
                const int r = r0 + h * 8;
                const float v0 = acc[mi][ni][h * 2 + 0];
                const float v1 = acc[mi][ni][h * 2 + 1];
                if (gc < OC) {
                    g_h[r * OC + gc] = v0;
                    g_h[r * OC + gc + 1] = v1;
                } else if (gc < 2 * OC) {
                    const int c = gc - OC;
                    g_z[r * OC + c] = v0 + __ldg(&b_rel[c]);
                    if (c + 1 < OC) g_z[r * OC + c + 1] = v1 + __ldg(&b_rel[c + 1]);
                }
            }
        }
    }
}

// ---------------------------------------------------------------------------
// GEMM2: out (4096 x 4096) = relu(z) @ W_dec + b_dec    grid (32, 32)
// Effective K = 208 (13 k16-steps): niter=4, last iteration 1 step.
// ---------------------------------------------------------------------------
__global__ __launch_bounds__(256) void gemm2_mma(const float* __restrict__ b_dec,
                                                 float* __restrict__ out) {
    extern __shared__ __align__(1024) char smem[];
    const uint32_t sb = smem_u32(smem);
    const int rowBase = blockIdx.y * 128;
    const int colBase = blockIdx.x * 128;

    float acc[4][4][4];
    #pragma unroll
    for (int i = 0; i < 4; i++)
        #pragma unroll
        for (int j = 0; j < 4; j++)
            #pragma unroll
            for (int t = 0; t < 4; t++) acc[i][j][t] = 0.f;

    mma_mainloop(acc, sb, 4, 1, g_zhi, g_zlo, rowBase, KPAD, g_wdhi, g_wdlo, colBase, KPAD);

    const int wid = threadIdx.x >> 5, lane = threadIdx.x & 31;
    const int wrbase = (wid >> 2) * 64, wcbase = (wid & 3) * 32;
    #pragma unroll
    for (int mi = 0; mi < 4; mi++) {
        #pragma unroll
        for (int ni = 0; ni < 4; ni++) {
            const int r0 = rowBase + wrbase + mi * 16 + (lane >> 2);
            const int gc = colBase + wcbase + ni * 8 + (lane & 3) * 2;
            const float b0 = __ldg(&b_dec[gc]);
            const float b1 = __ldg(&b_dec[gc + 1]);
            #pragma unroll
            for (int h = 0; h < 2; h++) {
                const int r = r0 + h * 8;
                float2 o;
                o.x = acc[mi][ni][h * 2 + 0] + b0;
                o.y = acc[mi][ni][h * 2 + 1] + b1;
                *reinterpret_cast<float2*>(&out[(size_t)r * NN + gc]) = o;
            }
        }
    }
}

// ---------------------------------------------------------------------------
// Launch.  Inputs: x, edge_index, edge_weight, W_rel, b_rel, W_root, W_dec, b_dec
// ---------------------------------------------------------------------------
extern "C" void kernel_launch(void* const* d_in, const int* in_sizes, int n_in,
                              void* d_out, int out_size) {
    const float* x      = (const float*)d_in[0];
    const int*   ei     = (const int*)  d_in[1];
    const float* ew     = (const float*)d_in[2];
    const float* W_rel  = (const float*)d_in[3];
    const float* b_rel  = (const float*)d_in[4];
    const float* W_root = (const float*)d_in[5];
    const float* W_dec  = (const float*)d_in[6];
    const float* b_dec  = (const float*)d_in[7];
    float* out = (float*)d_out;

    cudaFuncSetAttribute(gemm1_mma, cudaFuncAttributeMaxDynamicSharedMemorySize, SMEM_TOTAL);
    cudaFuncSetAttribute(gemm2_mma, cudaFuncAttributeMaxDynamicSharedMemorySize, SMEM_TOTAL);

    conv_pre_kernel<<<28672, 256>>>(x, W_rel, W_root, W_dec);

    gemm1_mma<<<dim3(4, 32), 256, SMEM_TOTAL>>>(b_rel);
    scatter_kernel<<<8192, 256>>>(ei, ew);
    conv_z_kernel<<<512, 256>>>();
    gemm2_mma<<<dim3(32, 32), 256, SMEM_TOTAL>>>(b_dec, out);
}